// round 7
// baseline (speedup 1.0000x reference)
#include <cuda_runtime.h>

// Problem constants
#define TT 64   // timesteps == layers
#define BB 128  // batch
#define HH 64   // hidden
#define NG 256  // 4*H gate width
#define GRID 128
#define NTHR 256

// Persistent device state
__device__ float g_hbuf[2][TT][BB][HH];  // h double-buffered by t parity
__device__ float g_c[TT][BB][HH];        // cell state per layer
__device__ float g_outs[BB][TT][HH];     // top-layer h per timestep
__device__ unsigned g_count;             // barrier arrival counter (monotone)

// smem layout (floats): As at [0, 128*68), Ws fixed at 8704 (+2*4096)
#define WS_OFF 8704
#define SMEM_FLOATS (WS_OFF + 2 * 4096)

__device__ __forceinline__ float sigf(float x) {
    return 1.0f / (1.0f + __expf(-x));
}
__device__ __forceinline__ float tanh_(float x) {
    return 2.0f / (1.0f + __expf(-2.0f * x)) - 1.0f;
}

// ---- packed f32x2 helpers (FFMA2; bit-exact vs 2x scalar FFMA) ----
__device__ __forceinline__ unsigned long long pk2(float v) {
    unsigned long long r;
    asm("mov.b64 %0, {%1, %1};" : "=l"(r) : "r"(__float_as_uint(v)));
    return r;
}
__device__ __forceinline__ unsigned long long pack2(float lo, float hi) {
    unsigned long long r;
    asm("mov.b64 %0, {%1, %2};" : "=l"(r)
        : "r"(__float_as_uint(lo)), "r"(__float_as_uint(hi)));
    return r;
}
__device__ __forceinline__ void fma2(unsigned long long& d,
                                     unsigned long long a, unsigned long long b) {
    asm("fma.rn.f32x2 %0, %1, %2, %0;" : "+l"(d) : "l"(a), "l"(b));
}
__device__ __forceinline__ float2 upk(unsigned long long v) {
    unsigned lo, hi;
    asm("mov.b64 {%0, %1}, %2;" : "=r"(lo), "=r"(hi) : "l"(v));
    return make_float2(__uint_as_float(lo), __uint_as_float(hi));
}

// ---------------------------------------------------------------------------
// Init: zero recurrent state + reset barrier counter. Runs each replay.
// ---------------------------------------------------------------------------
__global__ void init_kernel() {
    unsigned i = blockIdx.x * blockDim.x + threadIdx.x;
    if (i == 0) g_count = 0;
    unsigned stride = gridDim.x * blockDim.x;
    const float4 z = make_float4(0.f, 0.f, 0.f, 0.f);
    float4* a = reinterpret_cast<float4*>(&g_hbuf[0][0][0][0]);
    unsigned na = sizeof(g_hbuf) / 16;
    for (unsigned k = i; k < na; k += stride) a[k] = z;
    float4* b = reinterpret_cast<float4*>(&g_c[0][0][0]);
    unsigned nb = sizeof(g_c) / 16;
    for (unsigned k = i; k < nb; k += stride) b[k] = z;
}

// ---------------------------------------------------------------------------
// Grid-wide barrier: monotone target, release on arrive, acquire on spin.
// All GRID CTAs are resident (grid <= SM count) -> deadlock-free.
// ---------------------------------------------------------------------------
__device__ __forceinline__ void grid_barrier(unsigned target) {
    __syncthreads();
    if (threadIdx.x == 0) {
        __threadfence();                 // release: h/c stores visible in L2
        atomicAdd(&g_count, 1u);
        unsigned v;
        for (;;) {
            asm volatile("ld.acquire.gpu.u32 %0, [%1];"
                         : "=r"(v) : "l"(&g_count) : "memory");
            if (v >= target) break;
            __nanosleep(64);
        }
    }
    __syncthreads();
}

// ---------------------------------------------------------------------------
// One work unit: cell (l,t), batch rows [m0, m0+8*MR).
// Thread (tm=warp, tn=lane) owns rows tm*MR+[0..MR), col pair {2tn,2tn+1} of
// all 4 gates -> thread-local LSTM epilogue. K=128 unified GEMM, FFMA2,
// cp.async double-buffered W tiles, A staged transposed in smem.
// Cross-CTA reads use __ldcg (persistent kernel: L1 may be stale).
// ---------------------------------------------------------------------------
template <int MR>
__device__ __forceinline__ void do_unit(int l, int t, int m0,
                                        const float* __restrict__ x,
                                        const float* __restrict__ W0,
                                        const float* __restrict__ b0,
                                        const float* __restrict__ Wl,
                                        const float* __restrict__ bl,
                                        float* sm) {
    constexpr int M = 8 * MR;
    constexpr int ASTR = (MR >= 4) ? (M + 4) : (M + 1);
    float* As = sm;
    float* Ws = sm + WS_OFF;

    const int tid = threadIdx.x;
    const int tn = tid & 31;
    const int tm = tid >> 5;

    const float* Wbase = (l == 0) ? (W0 - 63 * NG)
                                  : (Wl + (size_t)(l - 1) * 128 * NG);
    const float* bias = (l == 0) ? b0 : (bl + (size_t)(l - 1) * NG);
    const int s0 = (l == 0) ? 4 : 0;

    unsigned ws_base = (unsigned)__cvta_generic_to_shared(Ws);

    // prefetch first W tile into buffer (s0&1)
    {
        const float* gW = Wbase + (size_t)s0 * 16 * NG;
        unsigned bofs = ((unsigned)(s0 & 1)) * 4096u * 4u;
#pragma unroll
        for (int i = 0; i < 4; ++i) {
            int idx = tid + i * 256;
            int row = idx >> 6, c4 = (idx & 63) << 2;
            unsigned dst = ws_base + bofs + (unsigned)((row << 8) + c4) * 4u;
            const float* src = gW + row * NG + c4;
            asm volatile("cp.async.cg.shared.global [%0], [%1], 16;\n"
                         :: "r"(dst), "l"(src));
        }
        asm volatile("cp.async.commit_group;\n");
    }

    // stage A transposed (k-major) while W tile is in flight (L2-coherent loads)
    const float* hown = &g_hbuf[(t & 1) ^ 1][l][m0][0];
    if (l == 0) {
        for (int e = tid; e < 64 * M; e += 256) {
            int m = e >> 6, k = e & 63;
            As[(64 + k) * ASTR + m] = __ldcg(hown + m * HH + k);
        }
    } else {
        const float* hbelow = &g_hbuf[t & 1][l - 1][m0][0];
        for (int e = tid; e < 128 * M; e += 256) {
            int m = e >> 7, k = e & 127;
            float v = (k < 64) ? __ldcg(hbelow + m * HH + k)
                               : __ldcg(hown + m * HH + (k - 64));
            As[k * ASTR + m] = v;
        }
    }

    // init accumulators with bias
    unsigned long long acc[MR][4];
#pragma unroll
    for (int g = 0; g < 4; ++g) {
        float2 bv = *reinterpret_cast<const float2*>(bias + g * 64 + 2 * tn);
        unsigned long long p = pack2(bv.x, bv.y);
#pragma unroll
        for (int r = 0; r < MR; ++r) acc[r][g] = p;
    }

    // layer 0: scalar x contribution (W0 row 0)
    if (l == 0) {
#pragma unroll
        for (int r = 0; r < MR; ++r) {
            float xv = x[(size_t)(m0 + tm * MR + r) * TT + t];
            unsigned long long x2 = pk2(xv);
#pragma unroll
            for (int g = 0; g < 4; ++g) {
                float2 wv = *reinterpret_cast<const float2*>(W0 + g * 64 + 2 * tn);
                fma2(acc[r][g], x2, pack2(wv.x, wv.y));
            }
        }
    }

    // main k-tile loop, double-buffered W
    for (int s = s0; s < 8; ++s) {
        if (s + 1 < 8) {
            const float* gW = Wbase + (size_t)(s + 1) * 16 * NG;
            unsigned bofs = ((unsigned)((s + 1) & 1)) * 4096u * 4u;
#pragma unroll
            for (int i = 0; i < 4; ++i) {
                int idx = tid + i * 256;
                int row = idx >> 6, c4 = (idx & 63) << 2;
                unsigned dst = ws_base + bofs + (unsigned)((row << 8) + c4) * 4u;
                const float* src = gW + row * NG + c4;
                asm volatile("cp.async.cg.shared.global [%0], [%1], 16;\n"
                             :: "r"(dst), "l"(src));
            }
            asm volatile("cp.async.commit_group;\n");
            asm volatile("cp.async.wait_group 1;\n");
        } else {
            asm volatile("cp.async.wait_group 0;\n");
        }
        __syncthreads();

        const float* wsb = Ws + (s & 1) * 4096;
        const float* asb = As + (s * 16) * ASTR;
#pragma unroll
        for (int kk = 0; kk < 16; ++kk) {
            const float* arow = asb + kk * ASTR + tm * MR;
            unsigned long long a2[MR];
            if constexpr (MR >= 4) {
#pragma unroll
                for (int q = 0; q < MR / 4; ++q) {
                    float4 av = *reinterpret_cast<const float4*>(arow + 4 * q);
                    a2[4 * q + 0] = pk2(av.x);
                    a2[4 * q + 1] = pk2(av.y);
                    a2[4 * q + 2] = pk2(av.z);
                    a2[4 * q + 3] = pk2(av.w);
                }
            } else {
#pragma unroll
                for (int r = 0; r < MR; ++r) a2[r] = pk2(arow[r]);
            }
            const float* wrow = wsb + kk * 256 + 2 * tn;
#pragma unroll
            for (int g = 0; g < 4; ++g) {
                unsigned long long w2 =
                    *reinterpret_cast<const unsigned long long*>(wrow + g * 64);
#pragma unroll
                for (int r = 0; r < MR; ++r) fma2(acc[r][g], a2[r], w2);
            }
        }
        __syncthreads();
    }

    // LSTM gate epilogue (gate order i, j, f, o)
#pragma unroll
    for (int r = 0; r < MR; ++r) {
        const int b = m0 + tm * MR + r;
        float2 zi = upk(acc[r][0]);
        float2 zj = upk(acc[r][1]);
        float2 zf = upk(acc[r][2]);
        float2 zo = upk(acc[r][3]);
        const float* cp = &g_c[l][b][2 * tn];
        float2 cold = make_float2(__ldcg(cp), __ldcg(cp + 1));
        float2 c2, h2;
        c2.x = cold.x * sigf(zf.x) + sigf(zi.x) * tanh_(zj.x);
        h2.x = tanh_(c2.x) * sigf(zo.x);
        c2.y = cold.y * sigf(zf.y) + sigf(zi.y) * tanh_(zj.y);
        h2.y = tanh_(c2.y) * sigf(zo.y);
        *reinterpret_cast<float2*>(&g_c[l][b][2 * tn]) = c2;
        *reinterpret_cast<float2*>(&g_hbuf[t & 1][l][b][2 * tn]) = h2;
        if (l == TT - 1)
            *reinterpret_cast<float2*>(&g_outs[b][t][2 * tn]) = h2;
    }
}

// ---------------------------------------------------------------------------
// Persistent kernel: 127 wavefronts + dense + loss, grid barriers in between.
// ---------------------------------------------------------------------------
__global__ __launch_bounds__(NTHR)
void lstm_persistent_kernel(const float* __restrict__ x,
                            const float* __restrict__ labels,
                            const float* __restrict__ W0,
                            const float* __restrict__ b0,
                            const float* __restrict__ Wl,
                            const float* __restrict__ bl,
                            const float* __restrict__ Wd,
                            const float* __restrict__ bd,
                            float* __restrict__ out, int out_size) {
    extern __shared__ float sm[];
    const int tid = threadIdx.x;

    for (int w = 0; w < 2 * TT - 1; ++w) {
        const int lo = (w > TT - 1) ? (w - (TT - 1)) : 0;
        const int hi = (w < TT - 1) ? w : (TT - 1);
        const int width = hi - lo + 1;
        // tile select: minimize per-step time (unit serial cyc ~ M*256)
        int mr, lgn;  // rows-per-thread, log2(chunks per 128 batch)
        if (width >= 33)      { mr = 8; lgn = 1; }
        else if (width >= 17) { mr = 4; lgn = 2; }
        else if (width >= 9)  { mr = 2; lgn = 3; }
        else                  { mr = 1; lgn = 4; }
        const int units = width << lgn;
        for (int u = blockIdx.x; u < units; u += GRID) {
            const int cell = u >> lgn;
            const int ch = u - (cell << lgn);
            const int l = lo + cell;
            const int t = w - l;
            const int m0 = ch * (8 * mr);
            switch (mr) {
                case 8: do_unit<8>(l, t, m0, x, W0, b0, Wl, bl, sm); break;
                case 4: do_unit<4>(l, t, m0, x, W0, b0, Wl, bl, sm); break;
                case 2: do_unit<2>(l, t, m0, x, W0, b0, Wl, bl, sm); break;
                default: do_unit<1>(l, t, m0, x, W0, b0, Wl, bl, sm); break;
            }
        }
        grid_barrier((unsigned)(w + 1) * GRID);
    }

    // dense(1) + relu per (b,t): first 32 CTAs cover 8192 outputs
    for (int idx = blockIdx.x * NTHR + tid; idx < BB * TT; idx += GRID * NTHR) {
        int b = idx >> 6, t = idx & 63;
        const float* o = &g_outs[b][t][0];
        const float* wv = Wd + (size_t)t * HH;
        float s = bd[t];
#pragma unroll
        for (int h = 0; h < HH; ++h) s += __ldcg(o + h) * wv[h];
        out[idx] = fmaxf(s, 0.0f);
    }
    grid_barrier((unsigned)(2 * TT) * GRID);

    // loss: CTA 0 only (deterministic reduction)
    if (blockIdx.x == 0) {
        float s = 0.0f;
        for (int i = tid; i < BB * TT; i += NTHR) {
            float d = labels[i] - __ldcg(out + i);
            s += d * d;
        }
        sm[tid] = s;
        __syncthreads();
        for (int off = NTHR / 2; off > 0; off >>= 1) {
            if (tid < off) sm[tid] += sm[tid + off];
            __syncthreads();
        }
        if (tid == 0 && out_size > BB * TT)
            out[BB * TT] = sm[0] / (float)(BB * TT);
    }
}

// ---------------------------------------------------------------------------
extern "C" void kernel_launch(void* const* d_in, const int* in_sizes, int n_in,
                              void* d_out, int out_size) {
    const float* x      = (const float*)d_in[0];
    const float* labels = (const float*)d_in[1];
    const float* W0     = (const float*)d_in[2];
    const float* b0     = (const float*)d_in[3];
    const float* Wl     = (const float*)d_in[4];
    const float* bl     = (const float*)d_in[5];
    const float* Wd     = (const float*)d_in[6];
    const float* bd     = (const float*)d_in[7];
    float* out = (float*)d_out;

    static bool attr_set = false;
    if (!attr_set) {
        cudaFuncSetAttribute(lstm_persistent_kernel,
                             cudaFuncAttributeMaxDynamicSharedMemorySize,
                             SMEM_FLOATS * 4);
        attr_set = true;
    }

    init_kernel<<<1024, 256>>>();
    lstm_persistent_kernel<<<GRID, NTHR, SMEM_FLOATS * 4>>>(
        x, labels, W0, b0, Wl, bl, Wd, bd, out, out_size);
}

// round 8
// speedup vs baseline: 1.1765x; 1.1765x over previous
#include <cuda_runtime.h>

// Problem constants
#define TT 64   // timesteps == layers
#define BB 128  // batch
#define HH 64   // hidden
#define NG 256  // 4*H gate width
#define GRID 128
#define NTHR 256

// smem layout (floats): As[64][128] row-major, then Ws[2][16][256]
#define WS_OFF 8192
#define SMEM_FLOATS (WS_OFF + 2 * 4096)   // 16384 floats = 64 KB

// Persistent device state
__device__ float g_hbuf[2][TT][BB][HH];   // h double-buffered by t parity
__device__ float g_c[TT][BB][HH];         // cell state per layer
__device__ float g_outs[BB][TT][HH];      // top-layer h per timestep
__device__ unsigned g_flags[GRID];        // per-CTA wave progress flags

__device__ __forceinline__ float sigf(float x) {
    return __fdividef(1.0f, 1.0f + __expf(-x));
}
__device__ __forceinline__ float tanh_(float x) {
    return __fdividef(2.0f, 1.0f + __expf(-2.0f * x)) - 1.0f;
}

// ---- packed f32x2 helpers ----
__device__ __forceinline__ unsigned long long pk2(float v) {
    unsigned long long r;
    asm("mov.b64 %0, {%1, %1};" : "=l"(r) : "r"(__float_as_uint(v)));
    return r;
}
__device__ __forceinline__ unsigned long long pack2(float lo, float hi) {
    unsigned long long r;
    asm("mov.b64 %0, {%1, %2};" : "=l"(r)
        : "r"(__float_as_uint(lo)), "r"(__float_as_uint(hi)));
    return r;
}
__device__ __forceinline__ void fma2(unsigned long long& d,
                                     unsigned long long a, unsigned long long b) {
    asm("fma.rn.f32x2 %0, %1, %2, %0;" : "+l"(d) : "l"(a), "l"(b));
}
__device__ __forceinline__ float2 upk(unsigned long long v) {
    unsigned lo, hi;
    asm("mov.b64 {%0, %1}, %2;" : "=r"(lo), "=r"(hi) : "l"(v));
    return make_float2(__uint_as_float(lo), __uint_as_float(hi));
}

__device__ __forceinline__ void cp_async16(unsigned dst_smem, const float* src) {
    asm volatile("cp.async.cg.shared.global [%0], [%1], 16;\n"
                 :: "r"(dst_smem), "l"(src));
}
__device__ __forceinline__ void cp_commit() {
    asm volatile("cp.async.commit_group;\n");
}

// ---------------------------------------------------------------------------
__global__ void init_kernel() {
    unsigned i = blockIdx.x * blockDim.x + threadIdx.x;
    if (i < GRID) g_flags[i] = 0;
    unsigned stride = gridDim.x * blockDim.x;
    const float4 z = make_float4(0.f, 0.f, 0.f, 0.f);
    float4* a = reinterpret_cast<float4*>(&g_hbuf[0][0][0][0]);
    unsigned na = sizeof(g_hbuf) / 16;
    for (unsigned k = i; k < na; k += stride) a[k] = z;
    float4* b = reinterpret_cast<float4*>(&g_c[0][0][0]);
    unsigned nb = sizeof(g_c) / 16;
    for (unsigned k = i; k < nb; k += stride) b[k] = z;
}

// ---------------------------------------------------------------------------
// Spread-flag grid barrier: each CTA publishes progress; threads 0..127 each
// poll one flag. All GRID CTAs resident (grid <= SM count) -> deadlock-free.
// ---------------------------------------------------------------------------
__device__ __forceinline__ void wave_barrier(unsigned val) {
    __syncthreads();
    if (threadIdx.x == 0) {
        __threadfence();
        asm volatile("st.release.gpu.global.u32 [%0], %1;"
                     :: "l"(&g_flags[blockIdx.x]), "r"(val) : "memory");
    }
    if (threadIdx.x < GRID) {
        unsigned v;
        for (;;) {
            asm volatile("ld.acquire.gpu.global.u32 %0, [%1];"
                         : "=r"(v) : "l"(&g_flags[threadIdx.x]) : "memory");
            if (v >= val) break;
            __nanosleep(32);
        }
    }
    __syncthreads();
}

// ---------------------------------------------------------------------------
// Wave geometry: layers [lo, lo+width), rows-per-thread mr, log2(chunks)
// ---------------------------------------------------------------------------
__device__ __forceinline__ void wave_geom(int w, int& lo, int& width,
                                          int& mr, int& lgc) {
    lo = (w > TT - 1) ? (w - (TT - 1)) : 0;
    int hi = (w < TT - 1) ? w : (TT - 1);
    width = hi - lo + 1;
    if (width >= 33)      { mr = 8; lgc = 1; }
    else if (width >= 17) { mr = 4; lgc = 2; }
    else if (width >= 9)  { mr = 2; lgc = 3; }
    else                  { mr = 1; lgc = 4; }
    // units = width << lgc, always <= 128
}

// ---------------------------------------------------------------------------
// One unit: cell (l,t), batch rows [m0, m0+8*MR). K=128 unified GEMM.
// As row-major [M][128] filled by cp.async (halves: below-h | own-h).
// pre: first W tile (s0) already prefetched into Ws buffer 0 last wave.
// ---------------------------------------------------------------------------
template <int MR>
__device__ __forceinline__ void do_unit(int l, int t, int m0, bool pre,
                                        const float* __restrict__ x,
                                        const float* __restrict__ W0,
                                        const float* __restrict__ b0,
                                        const float* __restrict__ Wl,
                                        const float* __restrict__ bl,
                                        float* sm) {
    constexpr int M = 8 * MR;
    float* As = sm;
    float* Ws = sm + WS_OFF;
    const int tid = threadIdx.x;
    const int tn = tid & 31;
    const int tm = tid >> 5;

    const float* Wbase = (l == 0) ? (W0 - 63 * NG)
                                  : (Wl + (size_t)(l - 1) * 128 * NG);
    const float* bias = (l == 0) ? b0 : (bl + (size_t)(l - 1) * NG);
    const int s0 = (l == 0) ? 4 : 0;
    unsigned ws_u = (unsigned)__cvta_generic_to_shared(Ws);
    unsigned as_u = (unsigned)__cvta_generic_to_shared(As);

    if (!pre) {  // W tile s0 -> buffer 0 (s0&1 == 0 always)
        const float* gW = Wbase + (size_t)s0 * 16 * NG;
#pragma unroll
        for (int i = 0; i < 4; ++i) {
            int idx = tid + i * NTHR;
            int row = idx >> 6, c4 = (idx & 63) << 2;
            cp_async16(ws_u + (unsigned)((row << 8) + c4) * 4u, gW + row * NG + c4);
        }
        cp_commit();
    }

    // A staging: cp.async (L2-coherent), row-major As[m][0:64]=below, [64:128]=own
    const float* hown = &g_hbuf[(t & 1) ^ 1][l][m0][0];
    if (l == 0) {
        for (int e = tid; e < M * 16; e += NTHR) {
            int row = e >> 4, c = (e & 15) << 2;
            cp_async16(as_u + (unsigned)(row * 128 + 64 + c) * 4u,
                       hown + row * HH + c);
        }
    } else {
        const float* hbelow = &g_hbuf[t & 1][l - 1][m0][0];
        for (int e = tid; e < M * 32; e += NTHR) {
            int row = e >> 5, q = e & 31;
            int half = q >> 4, c = (q & 15) << 2;
            const float* src = (half ? hown : hbelow) + row * HH + c;
            cp_async16(as_u + (unsigned)(row * 128 + half * 64 + c) * 4u, src);
        }
    }
    cp_commit();

    // prefetch c into registers (latency hidden under GEMM)
    float2 cold[MR];
#pragma unroll
    for (int r = 0; r < MR; ++r) {
        const float* cp = &g_c[l][m0 + tm * MR + r][2 * tn];
        cold[r].x = __ldcg(cp);
        cold[r].y = __ldcg(cp + 1);
    }

    // accumulators init with bias
    unsigned long long acc[MR][4];
#pragma unroll
    for (int g = 0; g < 4; ++g) {
        float2 bv = *reinterpret_cast<const float2*>(bias + g * 64 + 2 * tn);
        unsigned long long p = pack2(bv.x, bv.y);
#pragma unroll
        for (int r = 0; r < MR; ++r) acc[r][g] = p;
    }

    // layer 0: scalar x contribution (W0 row 0)
    if (l == 0) {
#pragma unroll
        for (int r = 0; r < MR; ++r) {
            float xv = x[(size_t)(m0 + tm * MR + r) * TT + t];
            unsigned long long x2 = pk2(xv);
#pragma unroll
            for (int g = 0; g < 4; ++g) {
                float2 wv = *reinterpret_cast<const float2*>(W0 + g * 64 + 2 * tn);
                fma2(acc[r][g], x2, pack2(wv.x, wv.y));
            }
        }
    }

    // main k-tile loop, double-buffered W
    for (int s = s0; s < 8; ++s) {
        if (s + 1 < 8) {
            const float* gW = Wbase + (size_t)(s + 1) * 16 * NG;
            unsigned bofs = ((unsigned)((s + 1) & 1)) * 4096u * 4u;
#pragma unroll
            for (int i = 0; i < 4; ++i) {
                int idx = tid + i * NTHR;
                int row = idx >> 6, c4 = (idx & 63) << 2;
                cp_async16(ws_u + bofs + (unsigned)((row << 8) + c4) * 4u,
                           gW + row * NG + c4);
            }
            cp_commit();
            asm volatile("cp.async.wait_group 1;\n");
        } else {
            asm volatile("cp.async.wait_group 0;\n");
        }
        __syncthreads();

        const float* wsb = Ws + (s & 1) * 4096;
        const float* abase = As + (tm * MR) * 128 + s * 16;
#pragma unroll
        for (int k4 = 0; k4 < 4; ++k4) {
            float4 a4[MR];
#pragma unroll
            for (int r = 0; r < MR; ++r)
                a4[r] = *reinterpret_cast<const float4*>(abase + r * 128 + k4 * 4);
#pragma unroll
            for (int j = 0; j < 4; ++j) {
                unsigned long long a2[MR];
#pragma unroll
                for (int r = 0; r < MR; ++r) {
                    const float* af = &a4[r].x;
                    a2[r] = pk2(af[j]);
                }
                const float* wrow = wsb + (k4 * 4 + j) * 256 + 2 * tn;
#pragma unroll
                for (int g = 0; g < 4; ++g) {
                    unsigned long long w2 =
                        *reinterpret_cast<const unsigned long long*>(wrow + g * 64);
#pragma unroll
                    for (int r = 0; r < MR; ++r) fma2(acc[r][g], a2[r], w2);
                }
            }
        }
        __syncthreads();
    }

    // LSTM gate epilogue (gate order i, j, f, o)
#pragma unroll
    for (int r = 0; r < MR; ++r) {
        const int b = m0 + tm * MR + r;
        float2 zi = upk(acc[r][0]);
        float2 zj = upk(acc[r][1]);
        float2 zf = upk(acc[r][2]);
        float2 zo = upk(acc[r][3]);
        float2 c2, h2;
        c2.x = cold[r].x * sigf(zf.x) + sigf(zi.x) * tanh_(zj.x);
        h2.x = tanh_(c2.x) * sigf(zo.x);
        c2.y = cold[r].y * sigf(zf.y) + sigf(zi.y) * tanh_(zj.y);
        h2.y = tanh_(c2.y) * sigf(zo.y);
        *reinterpret_cast<float2*>(&g_c[l][b][2 * tn]) = c2;
        *reinterpret_cast<float2*>(&g_hbuf[t & 1][l][b][2 * tn]) = h2;
        if (l == TT - 1)
            *reinterpret_cast<float2*>(&g_outs[b][t][2 * tn]) = h2;
    }
}

// ---------------------------------------------------------------------------
__global__ __launch_bounds__(NTHR)
void lstm_persistent_kernel(const float* __restrict__ x,
                            const float* __restrict__ labels,
                            const float* __restrict__ W0,
                            const float* __restrict__ b0,
                            const float* __restrict__ Wl,
                            const float* __restrict__ bl,
                            const float* __restrict__ Wd,
                            const float* __restrict__ bd,
                            float* __restrict__ out, int out_size) {
    extern __shared__ float sm[];
    const int tid = threadIdx.x;
    const int bid = blockIdx.x;

    bool pre = false;
    for (int w = 0; w < 2 * TT - 1; ++w) {
        int lo, width, mr, lgc;
        wave_geom(w, lo, width, mr, lgc);
        const int units = width << lgc;
        if (bid < units) {
            const int cell = bid >> lgc;
            const int ch = bid & ((1 << lgc) - 1);
            const int l = lo + cell;
            const int t = w - l;
            const int m0 = ch * (8 * mr);
            switch (mr) {
                case 8: do_unit<8>(l, t, m0, pre, x, W0, b0, Wl, bl, sm); break;
                case 4: do_unit<4>(l, t, m0, pre, x, W0, b0, Wl, bl, sm); break;
                case 2: do_unit<2>(l, t, m0, pre, x, W0, b0, Wl, bl, sm); break;
                default: do_unit<1>(l, t, m0, pre, x, W0, b0, Wl, bl, sm); break;
            }
        }
        // prefetch next wave's first W tile into Ws buffer 0 (static assignment)
        pre = false;
        if (w + 1 < 2 * TT - 1) {
            int lo2, width2, mr2, lgc2;
            wave_geom(w + 1, lo2, width2, mr2, lgc2);
            if (bid < (width2 << lgc2)) {
                const int l2 = lo2 + (bid >> lgc2);
                const float* Wb2 = (l2 == 0) ? (W0 - 63 * NG)
                                             : (Wl + (size_t)(l2 - 1) * 128 * NG);
                const int s02 = (l2 == 0) ? 4 : 0;
                const float* gW = Wb2 + (size_t)s02 * 16 * NG;
                unsigned ws_u = (unsigned)__cvta_generic_to_shared(sm + WS_OFF);
#pragma unroll
                for (int i = 0; i < 4; ++i) {
                    int idx = tid + i * NTHR;
                    int row = idx >> 6, c4 = (idx & 63) << 2;
                    cp_async16(ws_u + (unsigned)((row << 8) + c4) * 4u,
                               gW + row * NG + c4);
                }
                cp_commit();
                pre = true;
            }
        }
        wave_barrier((unsigned)(w + 1));
    }

    // dense(1) + relu per (b,t)
    for (int idx = bid * NTHR + tid; idx < BB * TT; idx += GRID * NTHR) {
        int b = idx >> 6, t = idx & 63;
        const float* o = &g_outs[b][t][0];
        const float* wv = Wd + (size_t)t * HH;
        float s = bd[t];
#pragma unroll
        for (int h = 0; h < HH; ++h) s += __ldcg(o + h) * wv[h];
        out[idx] = fmaxf(s, 0.0f);
    }
    wave_barrier((unsigned)(2 * TT));

    // loss: CTA 0 deterministic reduction
    if (bid == 0) {
        float s = 0.0f;
        for (int i = tid; i < BB * TT; i += NTHR) {
            float d = labels[i] - __ldcg(out + i);
            s += d * d;
        }
        sm[tid] = s;
        __syncthreads();
        for (int off = NTHR / 2; off > 0; off >>= 1) {
            if (tid < off) sm[tid] += sm[tid + off];
            __syncthreads();
        }
        if (tid == 0 && out_size > BB * TT)
            out[BB * TT] = sm[0] / (float)(BB * TT);
    }
}

// ---------------------------------------------------------------------------
extern "C" void kernel_launch(void* const* d_in, const int* in_sizes, int n_in,
                              void* d_out, int out_size) {
    const float* x      = (const float*)d_in[0];
    const float* labels = (const float*)d_in[1];
    const float* W0     = (const float*)d_in[2];
    const float* b0     = (const float*)d_in[3];
    const float* Wl     = (const float*)d_in[4];
    const float* bl     = (const float*)d_in[5];
    const float* Wd     = (const float*)d_in[6];
    const float* bd     = (const float*)d_in[7];
    float* out = (float*)d_out;

    static bool attr_set = false;
    if (!attr_set) {
        cudaFuncSetAttribute(lstm_persistent_kernel,
                             cudaFuncAttributeMaxDynamicSharedMemorySize,
                             SMEM_FLOATS * 4);
        attr_set = true;
    }

    init_kernel<<<1024, 256>>>();
    lstm_persistent_kernel<<<GRID, NTHR, SMEM_FLOATS * 4>>>(
        x, labels, W0, b0, Wl, bl, Wd, bd, out, out_size);
}

// round 9
// speedup vs baseline: 1.3294x; 1.1300x over previous
#include <cuda_runtime.h>

// Problem constants
#define TT 64   // timesteps == layers
#define BB 128  // batch
#define HH 64   // hidden
#define NG 256  // 4*H gate width
#define GRID 128
#define NTHR 256

// smem layout (floats): As[64][128] row-major, then Ws[2][16][256]
#define WS_OFF 8192
#define SMEM_FLOATS (WS_OFF + 2 * 4096)   // 16384 floats = 64 KB

// Persistent device state
__device__ float g_hbuf[2][TT][BB][HH];   // h double-buffered by t parity
__device__ float g_c[TT][BB][HH];         // cell state per layer
__device__ float g_outs[BB][TT][HH];      // top-layer h per timestep
__device__ unsigned g_done[TT][TT][16];   // per (l,t,8-row-group) completion
__device__ unsigned g_flags[GRID];        // final-barrier flags

__device__ __forceinline__ float sigf(float x) {
    return __fdividef(1.0f, 1.0f + __expf(-x));
}
__device__ __forceinline__ float tanh_(float x) {
    return __fdividef(2.0f, 1.0f + __expf(-2.0f * x)) - 1.0f;
}

// ---- packed f32x2 helpers ----
__device__ __forceinline__ unsigned long long pk2(float v) {
    unsigned long long r;
    asm("mov.b64 %0, {%1, %1};" : "=l"(r) : "r"(__float_as_uint(v)));
    return r;
}
__device__ __forceinline__ unsigned long long pack2(float lo, float hi) {
    unsigned long long r;
    asm("mov.b64 %0, {%1, %2};" : "=l"(r)
        : "r"(__float_as_uint(lo)), "r"(__float_as_uint(hi)));
    return r;
}
__device__ __forceinline__ void fma2(unsigned long long& d,
                                     unsigned long long a, unsigned long long b) {
    asm("fma.rn.f32x2 %0, %1, %2, %0;" : "+l"(d) : "l"(a), "l"(b));
}
__device__ __forceinline__ float2 upk(unsigned long long v) {
    unsigned lo, hi;
    asm("mov.b64 {%0, %1}, %2;" : "=r"(lo), "=r"(hi) : "l"(v));
    return make_float2(__uint_as_float(lo), __uint_as_float(hi));
}

__device__ __forceinline__ void cp_async16(unsigned dst_smem, const float* src) {
    asm volatile("cp.async.cg.shared.global [%0], [%1], 16;\n"
                 :: "r"(dst_smem), "l"(src));
}
__device__ __forceinline__ void cp_commit() {
    asm volatile("cp.async.commit_group;\n");
}

// ---------------------------------------------------------------------------
__global__ void init_kernel() {
    unsigned i = blockIdx.x * blockDim.x + threadIdx.x;
    unsigned stride = gridDim.x * blockDim.x;
    if (i < GRID) g_flags[i] = 0;
    unsigned* dn = &g_done[0][0][0];
    unsigned nd = sizeof(g_done) / 4;
    for (unsigned k = i; k < nd; k += stride) dn[k] = 0;
    const float4 z = make_float4(0.f, 0.f, 0.f, 0.f);
    float4* a = reinterpret_cast<float4*>(&g_hbuf[0][0][0][0]);
    unsigned na = sizeof(g_hbuf) / 16;
    for (unsigned k = i; k < na; k += stride) a[k] = z;
    float4* b = reinterpret_cast<float4*>(&g_c[0][0][0]);
    unsigned nb = sizeof(g_c) / 16;
    for (unsigned k = i; k < nb; k += stride) b[k] = z;
}

// ---------------------------------------------------------------------------
// Final global barrier (used twice: before dense, before loss).
// ---------------------------------------------------------------------------
__device__ __forceinline__ void wave_barrier(unsigned val) {
    __syncthreads();
    if (threadIdx.x == 0) {
        __threadfence();
        asm volatile("st.release.gpu.global.u32 [%0], %1;"
                     :: "l"(&g_flags[blockIdx.x]), "r"(val) : "memory");
    }
    if (threadIdx.x < GRID) {
        unsigned v;
        do {
            asm volatile("ld.acquire.gpu.global.u32 %0, [%1];"
                         : "=r"(v) : "l"(&g_flags[threadIdx.x]) : "memory");
        } while (v < val);
    }
    __syncthreads();
}

// ---------------------------------------------------------------------------
// Wave geometry: layers [lo, lo+width), rows-per-thread mr, log2(chunks)
// ---------------------------------------------------------------------------
__device__ __forceinline__ void wave_geom(int w, int& lo, int& width,
                                          int& mr, int& lgc) {
    lo = (w > TT - 1) ? (w - (TT - 1)) : 0;
    int hi = (w < TT - 1) ? w : (TT - 1);
    width = hi - lo + 1;
    if (width >= 33)      { mr = 8; lgc = 1; }
    else if (width >= 17) { mr = 4; lgc = 2; }
    else if (width >= 9)  { mr = 2; lgc = 3; }
    else                  { mr = 1; lgc = 4; }
    // units = width << lgc, always <= 128
}

// ---------------------------------------------------------------------------
// One unit: cell (l,t), batch rows [m0, m0+8*MR).
// Dataflow: W(s0) prefetch -> flag spin on producers -> A stage -> GEMM ->
// epilogue -> flag publish. Producers: (l-1,t) below-h, (l,t-1) own-h/c,
// anti-edge (l+1,t-2) (parity-buffer WAR).
// ---------------------------------------------------------------------------
template <int MR>
__device__ __forceinline__ void do_unit(int l, int t, int m0,
                                        const float* __restrict__ x,
                                        const float* __restrict__ W0,
                                        const float* __restrict__ b0,
                                        const float* __restrict__ Wl,
                                        const float* __restrict__ bl,
                                        float* sm) {
    constexpr int M = 8 * MR;
    float* As = sm;
    float* Ws = sm + WS_OFF;
    const int tid = threadIdx.x;
    const int tn = tid & 31;
    const int tm = tid >> 5;
    const int g0 = m0 >> 3;

    const float* Wbase = (l == 0) ? (W0 - 63 * NG)
                                  : (Wl + (size_t)(l - 1) * 128 * NG);
    const float* bias = (l == 0) ? b0 : (bl + (size_t)(l - 1) * NG);
    const int s0 = (l == 0) ? 4 : 0;
    unsigned ws_u = (unsigned)__cvta_generic_to_shared(Ws);
    unsigned as_u = (unsigned)__cvta_generic_to_shared(As);

    // W tile s0 prefetch (dep-free) -> overlaps the flag spin below
    {
        const float* gW = Wbase + (size_t)s0 * 16 * NG;
#pragma unroll
        for (int i = 0; i < 4; ++i) {
            int idx = tid + i * NTHR;
            int row = idx >> 6, c4 = (idx & 63) << 2;
            cp_async16(ws_u + (unsigned)((row << 8) + c4) * 4u, gW + row * NG + c4);
        }
        cp_commit();
    }

    // dataflow flag wait: up to 3 producers x MR row-group flags
    if (tid < 3 * MR) {
        int which = tid / MR;
        int g = g0 + (tid - which * MR);
        const unsigned* f = nullptr;
        if (which == 0)      { if (l > 0) f = &g_done[l - 1][t][g]; }
        else if (which == 1) { if (t > 0) f = &g_done[l][t - 1][g]; }
        else                 { if (l < TT - 1 && t >= 2) f = &g_done[l + 1][t - 2][g]; }
        if (f) {
            unsigned v;
            do {
                asm volatile("ld.acquire.gpu.global.u32 %0, [%1];"
                             : "=r"(v) : "l"(f) : "memory");
            } while (!v);
        }
    }
    __syncthreads();

    // A staging: cp.async (L2-coherent), row-major As[m][0:64]=below, [64:128]=own
    const float* hown = &g_hbuf[(t & 1) ^ 1][l][m0][0];
    if (l == 0) {
        for (int e = tid; e < M * 16; e += NTHR) {
            int row = e >> 4, c = (e & 15) << 2;
            cp_async16(as_u + (unsigned)(row * 128 + 64 + c) * 4u,
                       hown + row * HH + c);
        }
    } else {
        const float* hbelow = &g_hbuf[t & 1][l - 1][m0][0];
        for (int e = tid; e < M * 32; e += NTHR) {
            int row = e >> 5, q = e & 31;
            int half = q >> 4, c = (q & 15) << 2;
            const float* src = (half ? hown : hbelow) + row * HH + c;
            cp_async16(as_u + (unsigned)(row * 128 + half * 64 + c) * 4u, src);
        }
    }
    cp_commit();

    // prefetch c into registers (latency hidden under GEMM)
    float2 cold[MR];
#pragma unroll
    for (int r = 0; r < MR; ++r) {
        const float* cp = &g_c[l][m0 + tm * MR + r][2 * tn];
        cold[r].x = __ldcg(cp);
        cold[r].y = __ldcg(cp + 1);
    }

    // accumulators init with bias
    unsigned long long acc[MR][4];
#pragma unroll
    for (int g = 0; g < 4; ++g) {
        float2 bv = *reinterpret_cast<const float2*>(bias + g * 64 + 2 * tn);
        unsigned long long p = pack2(bv.x, bv.y);
#pragma unroll
        for (int r = 0; r < MR; ++r) acc[r][g] = p;
    }

    // layer 0: scalar x contribution (W0 row 0)
    if (l == 0) {
#pragma unroll
        for (int r = 0; r < MR; ++r) {
            float xv = x[(size_t)(m0 + tm * MR + r) * TT + t];
            unsigned long long x2 = pk2(xv);
#pragma unroll
            for (int g = 0; g < 4; ++g) {
                float2 wv = *reinterpret_cast<const float2*>(W0 + g * 64 + 2 * tn);
                fma2(acc[r][g], x2, pack2(wv.x, wv.y));
            }
        }
    }

    // main k-tile loop, double-buffered W
    for (int s = s0; s < 8; ++s) {
        if (s + 1 < 8) {
            const float* gW = Wbase + (size_t)(s + 1) * 16 * NG;
            unsigned bofs = ((unsigned)((s + 1) & 1)) * 4096u * 4u;
#pragma unroll
            for (int i = 0; i < 4; ++i) {
                int idx = tid + i * NTHR;
                int row = idx >> 6, c4 = (idx & 63) << 2;
                cp_async16(ws_u + bofs + (unsigned)((row << 8) + c4) * 4u,
                           gW + row * NG + c4);
            }
            cp_commit();
            asm volatile("cp.async.wait_group 1;\n");
        } else {
            asm volatile("cp.async.wait_group 0;\n");
        }
        __syncthreads();

        const float* wsb = Ws + (s & 1) * 4096;
        const float* abase = As + (tm * MR) * 128 + s * 16;
#pragma unroll
        for (int k4 = 0; k4 < 4; ++k4) {
            float4 a4[MR];
#pragma unroll
            for (int r = 0; r < MR; ++r)
                a4[r] = *reinterpret_cast<const float4*>(abase + r * 128 + k4 * 4);
#pragma unroll
            for (int j = 0; j < 4; ++j) {
                unsigned long long a2[MR];
#pragma unroll
                for (int r = 0; r < MR; ++r) {
                    const float* af = &a4[r].x;
                    a2[r] = pk2(af[j]);
                }
                const float* wrow = wsb + (k4 * 4 + j) * 256 + 2 * tn;
#pragma unroll
                for (int g = 0; g < 4; ++g) {
                    unsigned long long w2 =
                        *reinterpret_cast<const unsigned long long*>(wrow + g * 64);
#pragma unroll
                    for (int r = 0; r < MR; ++r) fma2(acc[r][g], a2[r], w2);
                }
            }
        }
        __syncthreads();
    }

    // LSTM gate epilogue (gate order i, j, f, o)
#pragma unroll
    for (int r = 0; r < MR; ++r) {
        const int b = m0 + tm * MR + r;
        float2 zi = upk(acc[r][0]);
        float2 zj = upk(acc[r][1]);
        float2 zf = upk(acc[r][2]);
        float2 zo = upk(acc[r][3]);
        float2 c2, h2;
        c2.x = cold[r].x * sigf(zf.x) + sigf(zi.x) * tanh_(zj.x);
        h2.x = tanh_(c2.x) * sigf(zo.x);
        c2.y = cold[r].y * sigf(zf.y) + sigf(zi.y) * tanh_(zj.y);
        h2.y = tanh_(c2.y) * sigf(zo.y);
        *reinterpret_cast<float2*>(&g_c[l][b][2 * tn]) = c2;
        *reinterpret_cast<float2*>(&g_hbuf[t & 1][l][b][2 * tn]) = h2;
        if (l == TT - 1)
            *reinterpret_cast<float2*>(&g_outs[b][t][2 * tn]) = h2;
    }

    // publish completion flags for my row-groups
    __syncthreads();
    if (tid < MR) {
        __threadfence();
        asm volatile("st.release.gpu.global.u32 [%0], %1;"
                     :: "l"(&g_done[l][t][g0 + tid]), "r"(1u) : "memory");
    }
}

// ---------------------------------------------------------------------------
// Persistent dataflow kernel: cells gated by flags, no global wave barriers.
// ---------------------------------------------------------------------------
__global__ __launch_bounds__(NTHR)
void lstm_persistent_kernel(const float* __restrict__ x,
                            const float* __restrict__ labels,
                            const float* __restrict__ W0,
                            const float* __restrict__ b0,
                            const float* __restrict__ Wl,
                            const float* __restrict__ bl,
                            const float* __restrict__ Wd,
                            const float* __restrict__ bd,
                            float* __restrict__ out, int out_size) {
    extern __shared__ float sm[];
    const int tid = threadIdx.x;
    const int bid = blockIdx.x;

    unsigned off = 0;  // round-robin rotation: balances units across CTAs
    for (int w = 0; w < 2 * TT - 1; ++w) {
        int lo, width, mr, lgc;
        wave_geom(w, lo, width, mr, lgc);
        const int units = width << lgc;
        int u = bid - (int)(off & (GRID - 1));
        if (u < 0) u += GRID;
        if (u < units) {
            const int cell = u >> lgc;
            const int ch = u & ((1 << lgc) - 1);
            const int l = lo + cell;
            const int t = w - l;
            const int m0 = ch * (8 * mr);
            switch (mr) {
                case 8: do_unit<8>(l, t, m0, x, W0, b0, Wl, bl, sm); break;
                case 4: do_unit<4>(l, t, m0, x, W0, b0, Wl, bl, sm); break;
                case 2: do_unit<2>(l, t, m0, x, W0, b0, Wl, bl, sm); break;
                default: do_unit<1>(l, t, m0, x, W0, b0, Wl, bl, sm); break;
            }
        }
        off += (unsigned)units;
    }

    wave_barrier(1u);  // all cells done -> g_outs complete

    // dense(1) + relu per (b,t)
    for (int idx = bid * NTHR + tid; idx < BB * TT; idx += GRID * NTHR) {
        int b = idx >> 6, t = idx & 63;
        const float* o = &g_outs[b][t][0];
        const float* wv = Wd + (size_t)t * HH;
        float s = bd[t];
#pragma unroll
        for (int h = 0; h < HH; ++h) s += __ldcg(o + h) * wv[h];
        out[idx] = fmaxf(s, 0.0f);
    }
    wave_barrier(2u);

    // loss: CTA 0 deterministic reduction
    if (bid == 0) {
        float s = 0.0f;
        for (int i = tid; i < BB * TT; i += NTHR) {
            float d = labels[i] - __ldcg(out + i);
            s += d * d;
        }
        sm[tid] = s;
        __syncthreads();
        for (int off2 = NTHR / 2; off2 > 0; off2 >>= 1) {
            if (tid < off2) sm[tid] += sm[tid + off2];
            __syncthreads();
        }
        if (tid == 0 && out_size > BB * TT)
            out[BB * TT] = sm[0] / (float)(BB * TT);
    }
}

// ---------------------------------------------------------------------------
extern "C" void kernel_launch(void* const* d_in, const int* in_sizes, int n_in,
                              void* d_out, int out_size) {
    const float* x      = (const float*)d_in[0];
    const float* labels = (const float*)d_in[1];
    const float* W0     = (const float*)d_in[2];
    const float* b0     = (const float*)d_in[3];
    const float* Wl     = (const float*)d_in[4];
    const float* bl     = (const float*)d_in[5];
    const float* Wd     = (const float*)d_in[6];
    const float* bd     = (const float*)d_in[7];
    float* out = (float*)d_out;

    static bool attr_set = false;
    if (!attr_set) {
        cudaFuncSetAttribute(lstm_persistent_kernel,
                             cudaFuncAttributeMaxDynamicSharedMemorySize,
                             SMEM_FLOATS * 4);
        attr_set = true;
    }

    init_kernel<<<1024, 256>>>();
    lstm_persistent_kernel<<<GRID, NTHR, SMEM_FLOATS * 4>>>(
        x, labels, W0, b0, Wl, bl, Wd, bd, out, out_size);
}

// round 10
// speedup vs baseline: 1.3821x; 1.0396x over previous
#include <cuda_runtime.h>

// Problem constants
#define TT 64   // timesteps == layers
#define BB 128  // batch
#define HH 64   // hidden
#define NG 256  // 4*H gate width
#define GRID 256
#define NTHR 256

// smem layout (floats): As[32][128] row-major, then Ws[2][16][256]
#define WS_OFF 4096
#define SMEM_FLOATS (WS_OFF + 2 * 4096)   // 12288 floats = 48 KB

// Persistent device state
__device__ float g_hbuf[2][TT][BB][HH];   // h double-buffered by t parity
__device__ float g_c[TT][BB][HH];         // cell state per layer
__device__ float g_outs[BB][TT][HH];      // top-layer h per timestep
__device__ unsigned g_done[TT][TT][16];   // per (l,t,8-row-group) completion
__device__ unsigned g_flags[GRID];        // final-barrier flags

__device__ __forceinline__ float sigf(float x) {
    return __fdividef(1.0f, 1.0f + __expf(-x));
}
__device__ __forceinline__ float tanh_(float x) {
    return __fdividef(2.0f, 1.0f + __expf(-2.0f * x)) - 1.0f;
}

// ---- packed f32x2 helpers ----
__device__ __forceinline__ unsigned long long pk2(float v) {
    unsigned long long r;
    asm("mov.b64 %0, {%1, %1};" : "=l"(r) : "r"(__float_as_uint(v)));
    return r;
}
__device__ __forceinline__ unsigned long long pack2(float lo, float hi) {
    unsigned long long r;
    asm("mov.b64 %0, {%1, %2};" : "=l"(r)
        : "r"(__float_as_uint(lo)), "r"(__float_as_uint(hi)));
    return r;
}
__device__ __forceinline__ void fma2(unsigned long long& d,
                                     unsigned long long a, unsigned long long b) {
    asm("fma.rn.f32x2 %0, %1, %2, %0;" : "+l"(d) : "l"(a), "l"(b));
}
__device__ __forceinline__ float2 upk(unsigned long long v) {
    unsigned lo, hi;
    asm("mov.b64 {%0, %1}, %2;" : "=r"(lo), "=r"(hi) : "l"(v));
    return make_float2(__uint_as_float(lo), __uint_as_float(hi));
}

__device__ __forceinline__ void cp_async16(unsigned dst_smem, const float* src) {
    asm volatile("cp.async.cg.shared.global [%0], [%1], 16;\n"
                 :: "r"(dst_smem), "l"(src));
}
__device__ __forceinline__ void cp_commit() {
    asm volatile("cp.async.commit_group;\n");
}

// ---------------------------------------------------------------------------
__global__ void init_kernel() {
    unsigned i = blockIdx.x * blockDim.x + threadIdx.x;
    unsigned stride = gridDim.x * blockDim.x;
    if (i < GRID) g_flags[i] = 0;
    unsigned* dn = &g_done[0][0][0];
    unsigned nd = sizeof(g_done) / 4;
    for (unsigned k = i; k < nd; k += stride) dn[k] = 0;
    const float4 z = make_float4(0.f, 0.f, 0.f, 0.f);
    float4* a = reinterpret_cast<float4*>(&g_hbuf[0][0][0][0]);
    unsigned na = sizeof(g_hbuf) / 16;
    for (unsigned k = i; k < na; k += stride) a[k] = z;
    float4* b = reinterpret_cast<float4*>(&g_c[0][0][0]);
    unsigned nb = sizeof(g_c) / 16;
    for (unsigned k = i; k < nb; k += stride) b[k] = z;
}

// ---------------------------------------------------------------------------
// Final global barrier (used twice: before dense, before loss).
// ---------------------------------------------------------------------------
__device__ __forceinline__ void wave_barrier(unsigned val) {
    __syncthreads();
    if (threadIdx.x == 0) {
        asm volatile("st.release.gpu.global.u32 [%0], %1;"
                     :: "l"(&g_flags[blockIdx.x]), "r"(val) : "memory");
    }
    if (threadIdx.x < GRID) {
        unsigned v;
        do {
            asm volatile("ld.acquire.gpu.global.u32 %0, [%1];"
                         : "=r"(v) : "l"(&g_flags[threadIdx.x]) : "memory");
        } while (v < val);
    }
    __syncthreads();
}

// ---------------------------------------------------------------------------
// Wave geometry: layers [lo, lo+width), rows-per-thread mr, log2(chunks).
// Max MR is 4 (32-row chunks) so wide waves produce up to 256 units -> both
// co-resident CTAs per SM get work. Min chunk is 8 rows (flag granularity).
// ---------------------------------------------------------------------------
__device__ __forceinline__ void wave_geom(int w, int& lo, int& width,
                                          int& mr, int& lgc) {
    lo = (w > TT - 1) ? (w - (TT - 1)) : 0;
    int hi = (w < TT - 1) ? w : (TT - 1);
    width = hi - lo + 1;
    if (width >= 33)      { mr = 4; lgc = 2; }   // units = 4*width  (132..256)
    else if (width >= 17) { mr = 2; lgc = 3; }   // units = 8*width  (136..256)
    else                  { mr = 1; lgc = 4; }   // units = 16*width (16..256)
}

// ---------------------------------------------------------------------------
// One unit: cell (l,t), batch rows [m0, m0+8*MR).
// Dataflow: W(s0) prefetch -> flag spin on producers -> A stage -> GEMM ->
// epilogue -> flag publish. Producers: (l-1,t) below-h, (l,t-1) own-h/c,
// anti-edge (l+1,t-2) (parity-buffer WAR), all at matching row groups.
// ---------------------------------------------------------------------------
template <int MR>
__device__ __forceinline__ void do_unit(int l, int t, int m0,
                                        const float* __restrict__ x,
                                        const float* __restrict__ W0,
                                        const float* __restrict__ b0,
                                        const float* __restrict__ Wl,
                                        const float* __restrict__ bl,
                                        float* sm) {
    constexpr int M = 8 * MR;
    float* As = sm;
    float* Ws = sm + WS_OFF;
    const int tid = threadIdx.x;
    const int tn = tid & 31;
    const int tm = tid >> 5;
    const int g0 = m0 >> 3;

    const float* Wbase = (l == 0) ? (W0 - 63 * NG)
                                  : (Wl + (size_t)(l - 1) * 128 * NG);
    const float* bias = (l == 0) ? b0 : (bl + (size_t)(l - 1) * NG);
    const int s0 = (l == 0) ? 4 : 0;
    unsigned ws_u = (unsigned)__cvta_generic_to_shared(Ws);
    unsigned as_u = (unsigned)__cvta_generic_to_shared(As);

    // W tile s0 prefetch (dep-free) -> overlaps the flag spin below
    {
        const float* gW = Wbase + (size_t)s0 * 16 * NG;
#pragma unroll
        for (int i = 0; i < 4; ++i) {
            int idx = tid + i * NTHR;
            int row = idx >> 6, c4 = (idx & 63) << 2;
            cp_async16(ws_u + (unsigned)((row << 8) + c4) * 4u, gW + row * NG + c4);
        }
        cp_commit();
    }

    // dataflow flag wait: up to 3 producers x MR row-group flags
    if (tid < 3 * MR) {
        int which = tid / MR;
        int g = g0 + (tid - which * MR);
        const unsigned* f = nullptr;
        if (which == 0)      { if (l > 0) f = &g_done[l - 1][t][g]; }
        else if (which == 1) { if (t > 0) f = &g_done[l][t - 1][g]; }
        else                 { if (l < TT - 1 && t >= 2) f = &g_done[l + 1][t - 2][g]; }
        if (f) {
            unsigned v;
            do {
                asm volatile("ld.acquire.gpu.global.u32 %0, [%1];"
                             : "=r"(v) : "l"(f) : "memory");
            } while (!v);
        }
    }
    __syncthreads();

    // A staging: cp.async (L2-coherent), row-major As[m][0:64]=below, [64:128]=own
    const float* hown = &g_hbuf[(t & 1) ^ 1][l][m0][0];
    if (l == 0) {
        for (int e = tid; e < M * 16; e += NTHR) {
            int row = e >> 4, c = (e & 15) << 2;
            cp_async16(as_u + (unsigned)(row * 128 + 64 + c) * 4u,
                       hown + row * HH + c);
        }
    } else {
        const float* hbelow = &g_hbuf[t & 1][l - 1][m0][0];
        for (int e = tid; e < M * 32; e += NTHR) {
            int row = e >> 5, q = e & 31;
            int half = q >> 4, c = (q & 15) << 2;
            const float* src = (half ? hown : hbelow) + row * HH + c;
            cp_async16(as_u + (unsigned)(row * 128 + half * 64 + c) * 4u, src);
        }
    }
    cp_commit();

    // prefetch c into registers (latency hidden under GEMM)
    float2 cold[MR];
#pragma unroll
    for (int r = 0; r < MR; ++r) {
        const float* cp = &g_c[l][m0 + tm * MR + r][2 * tn];
        cold[r].x = __ldcg(cp);
        cold[r].y = __ldcg(cp + 1);
    }

    // accumulators init with bias
    unsigned long long acc[MR][4];
#pragma unroll
    for (int g = 0; g < 4; ++g) {
        float2 bv = *reinterpret_cast<const float2*>(bias + g * 64 + 2 * tn);
        unsigned long long p = pack2(bv.x, bv.y);
#pragma unroll
        for (int r = 0; r < MR; ++r) acc[r][g] = p;
    }

    // layer 0: scalar x contribution (W0 row 0)
    if (l == 0) {
#pragma unroll
        for (int r = 0; r < MR; ++r) {
            float xv = x[(size_t)(m0 + tm * MR + r) * TT + t];
            unsigned long long x2 = pk2(xv);
#pragma unroll
            for (int g = 0; g < 4; ++g) {
                float2 wv = *reinterpret_cast<const float2*>(W0 + g * 64 + 2 * tn);
                fma2(acc[r][g], x2, pack2(wv.x, wv.y));
            }
        }
    }

    // main k-tile loop, double-buffered W
    for (int s = s0; s < 8; ++s) {
        if (s + 1 < 8) {
            const float* gW = Wbase + (size_t)(s + 1) * 16 * NG;
            unsigned bofs = ((unsigned)((s + 1) & 1)) * 4096u * 4u;
#pragma unroll
            for (int i = 0; i < 4; ++i) {
                int idx = tid + i * NTHR;
                int row = idx >> 6, c4 = (idx & 63) << 2;
                cp_async16(ws_u + bofs + (unsigned)((row << 8) + c4) * 4u,
                           gW + row * NG + c4);
            }
            cp_commit();
            asm volatile("cp.async.wait_group 1;\n");
        } else {
            asm volatile("cp.async.wait_group 0;\n");
        }
        __syncthreads();

        const float* wsb = Ws + (s & 1) * 4096;
        const float* abase = As + (tm * MR) * 128 + s * 16;
#pragma unroll
        for (int k4 = 0; k4 < 4; ++k4) {
            float4 a4[MR];
#pragma unroll
            for (int r = 0; r < MR; ++r)
                a4[r] = *reinterpret_cast<const float4*>(abase + r * 128 + k4 * 4);
#pragma unroll
            for (int j = 0; j < 4; ++j) {
                unsigned long long a2[MR];
#pragma unroll
                for (int r = 0; r < MR; ++r) {
                    const float* af = &a4[r].x;
                    a2[r] = pk2(af[j]);
                }
                const float* wrow = wsb + (k4 * 4 + j) * 256 + 2 * tn;
#pragma unroll
                for (int g = 0; g < 4; ++g) {
                    unsigned long long w2 =
                        *reinterpret_cast<const unsigned long long*>(wrow + g * 64);
#pragma unroll
                    for (int r = 0; r < MR; ++r) fma2(acc[r][g], a2[r], w2);
                }
            }
        }
        __syncthreads();
    }

    // LSTM gate epilogue (gate order i, j, f, o)
#pragma unroll
    for (int r = 0; r < MR; ++r) {
        const int b = m0 + tm * MR + r;
        float2 zi = upk(acc[r][0]);
        float2 zj = upk(acc[r][1]);
        float2 zf = upk(acc[r][2]);
        float2 zo = upk(acc[r][3]);
        float2 c2, h2;
        c2.x = cold[r].x * sigf(zf.x) + sigf(zi.x) * tanh_(zj.x);
        h2.x = tanh_(c2.x) * sigf(zo.x);
        c2.y = cold[r].y * sigf(zf.y) + sigf(zi.y) * tanh_(zj.y);
        h2.y = tanh_(c2.y) * sigf(zo.y);
        *reinterpret_cast<float2*>(&g_c[l][b][2 * tn]) = c2;
        *reinterpret_cast<float2*>(&g_hbuf[t & 1][l][b][2 * tn]) = h2;
        if (l == TT - 1)
            *reinterpret_cast<float2*>(&g_outs[b][t][2 * tn]) = h2;
    }

    // publish completion flags for my row-groups (release orders prior stores)
    __syncthreads();
    if (tid < MR) {
        asm volatile("st.release.gpu.global.u32 [%0], %1;"
                     :: "l"(&g_done[l][t][g0 + tid]), "r"(1u) : "memory");
    }
}

// ---------------------------------------------------------------------------
// Persistent dataflow kernel: cells gated by flags, no global wave barriers.
// ---------------------------------------------------------------------------
__global__ __launch_bounds__(NTHR, 2)
void lstm_persistent_kernel(const float* __restrict__ x,
                            const float* __restrict__ labels,
                            const float* __restrict__ W0,
                            const float* __restrict__ b0,
                            const float* __restrict__ Wl,
                            const float* __restrict__ bl,
                            const float* __restrict__ Wd,
                            const float* __restrict__ bd,
                            float* __restrict__ out, int out_size) {
    extern __shared__ float sm[];
    const int tid = threadIdx.x;
    const int bid = blockIdx.x;

    unsigned off = 0;  // round-robin rotation: balances units across CTAs
    for (int w = 0; w < 2 * TT - 1; ++w) {
        int lo, width, mr, lgc;
        wave_geom(w, lo, width, mr, lgc);
        const int units = width << lgc;
        int u = bid - (int)(off & (GRID - 1));
        if (u < 0) u += GRID;
        if (u < units) {
            const int cell = u >> lgc;
            const int ch = u & ((1 << lgc) - 1);
            const int l = lo + cell;
            const int t = w - l;
            const int m0 = ch * (8 * mr);
            switch (mr) {
                case 4: do_unit<4>(l, t, m0, x, W0, b0, Wl, bl, sm); break;
                case 2: do_unit<2>(l, t, m0, x, W0, b0, Wl, bl, sm); break;
                default: do_unit<1>(l, t, m0, x, W0, b0, Wl, bl, sm); break;
            }
        }
        off += (unsigned)units;
    }

    wave_barrier(1u);  // all cells done -> g_outs complete

    // dense(1) + relu per (b,t)
    for (int idx = bid * NTHR + tid; idx < BB * TT; idx += GRID * NTHR) {
        int b = idx >> 6, t = idx & 63;
        const float* o = &g_outs[b][t][0];
        const float* wv = Wd + (size_t)t * HH;
        float s = bd[t];
#pragma unroll
        for (int h = 0; h < HH; ++h) s += __ldcg(o + h) * wv[h];
        out[idx] = fmaxf(s, 0.0f);
    }
    wave_barrier(2u);

    // loss: CTA 0 deterministic reduction
    if (bid == 0) {
        float s = 0.0f;
        for (int i = tid; i < BB * TT; i += NTHR) {
            float d = labels[i] - __ldcg(out + i);
            s += d * d;
        }
        sm[tid] = s;
        __syncthreads();
        for (int off2 = NTHR / 2; off2 > 0; off2 >>= 1) {
            if (tid < off2) sm[tid] += sm[tid + off2];
            __syncthreads();
        }
        if (tid == 0 && out_size > BB * TT)
            out[BB * TT] = sm[0] / (float)(BB * TT);
    }
}

// ---------------------------------------------------------------------------
extern "C" void kernel_launch(void* const* d_in, const int* in_sizes, int n_in,
                              void* d_out, int out_size) {
    const float* x      = (const float*)d_in[0];
    const float* labels = (const float*)d_in[1];
    const float* W0     = (const float*)d_in[2];
    const float* b0     = (const float*)d_in[3];
    const float* Wl     = (const float*)d_in[4];
    const float* bl     = (const float*)d_in[5];
    const float* Wd     = (const float*)d_in[6];
    const float* bd     = (const float*)d_in[7];
    float* out = (float*)d_out;

    static bool attr_set = false;
    if (!attr_set) {
        cudaFuncSetAttribute(lstm_persistent_kernel,
                             cudaFuncAttributeMaxDynamicSharedMemorySize,
                             SMEM_FLOATS * 4);
        attr_set = true;
    }

    init_kernel<<<1024, 256>>>();
    lstm_persistent_kernel<<<GRID, NTHR, SMEM_FLOATS * 4>>>(
        x, labels, W0, b0, Wl, bl, Wd, bd, out, out_size);
}

// round 14
// speedup vs baseline: 2.1098x; 1.5265x over previous
#include <cuda_runtime.h>
#include <cuda_bf16.h>

#define TT 64
#define BB 128
#define HH 64
#define NG 256
#define GRID 256
#define NTHR 256

// smem: A images 16KB @0, W double-buffer 64KB @16KB. Z (33KB) aliases @0 in epilogue.
#define SMEM_BYTES (16384 + 65536)
#define ZSTRIDE 258   // f32 stride per Z row (8B aligned, 2-way LDS conflicts max)

// ---------------- persistent device state ----------------
__device__ __nv_bfloat16 g_h[2][2][TT][BB][HH];      // [plane hi/lo][t-parity][l][b][hc]
__device__ float g_c[TT][BB][HH];
__device__ float g_outs[BB][TT][HH];
// W images: [l][ktile 0..3][plane][nb 0..3][32k][64n] bf16, SW128-swizzled per 4KB subtile
__device__ __nv_bfloat16 g_Wimg[TT][4][2][4][2048];
__device__ float g_bias[TT][NG];                      // gate-interleaved n' = hc*4+g
__device__ float g_w0r0[NG];                          // W0 row 0, gate-interleaved
__device__ unsigned g_done[TT][TT][4];                // per (l,t,32-row chunk)
__device__ unsigned g_flags[GRID];

// ---------------- helpers ----------------
__device__ __forceinline__ unsigned swz(unsigned b) { return b ^ ((b >> 3) & 0x70); }
__device__ __forceinline__ unsigned smem_u32(const void* p) {
    unsigned a;
    asm("{ .reg .u64 t; cvta.to.shared.u64 t, %1; cvt.u32.u64 %0, t; }" : "=r"(a) : "l"(p));
    return a;
}
__device__ __forceinline__ void cp_async16(unsigned dst, const void* src) {
    asm volatile("cp.async.cg.shared.global [%0], [%1], 16;\n" :: "r"(dst), "l"(src));
}
__device__ __forceinline__ void cp_commit() { asm volatile("cp.async.commit_group;\n"); }
__device__ __forceinline__ float sigf(float x) { return __fdividef(1.0f, 1.0f + __expf(-x)); }
__device__ __forceinline__ float tanh_(float x) { return __fdividef(2.0f, 1.0f + __expf(-2.0f * x)) - 1.0f; }

__device__ __forceinline__ void ldsm_x4(unsigned* r, unsigned addr) {
    asm volatile("ldmatrix.sync.aligned.m8n8.x4.shared.b16 {%0,%1,%2,%3}, [%4];"
                 : "=r"(r[0]), "=r"(r[1]), "=r"(r[2]), "=r"(r[3]) : "r"(addr));
}
__device__ __forceinline__ void ldsm_x4_t(unsigned* r, unsigned addr) {
    asm volatile("ldmatrix.sync.aligned.m8n8.x4.trans.shared.b16 {%0,%1,%2,%3}, [%4];"
                 : "=r"(r[0]), "=r"(r[1]), "=r"(r[2]), "=r"(r[3]) : "r"(addr));
}
__device__ __forceinline__ void mma_bf16(float* c, const unsigned* a, unsigned b0, unsigned b1) {
    asm volatile(
        "mma.sync.aligned.m16n8k16.row.col.f32.bf16.bf16.f32 "
        "{%0,%1,%2,%3}, {%4,%5,%6,%7}, {%8,%9}, {%0,%1,%2,%3};"
        : "+f"(c[0]), "+f"(c[1]), "+f"(c[2]), "+f"(c[3])
        : "r"(a[0]), "r"(a[1]), "r"(a[2]), "r"(a[3]), "r"(b0), "r"(b1));
}

// ---------------------------------------------------------------------------
__global__ void init_state_kernel() {
    unsigned i = blockIdx.x * blockDim.x + threadIdx.x;
    unsigned stride = gridDim.x * blockDim.x;
    if (i < GRID) g_flags[i] = 0;
    unsigned* dn = &g_done[0][0][0];
    for (unsigned k = i; k < sizeof(g_done) / 4; k += stride) dn[k] = 0;
    uint4 z = make_uint4(0, 0, 0, 0);
    uint4* hh = reinterpret_cast<uint4*>(&g_h[0][0][0][0][0]);
    for (unsigned k = i; k < sizeof(g_h) / 16; k += stride) hh[k] = z;
    uint4* cc = reinterpret_cast<uint4*>(&g_c[0][0][0]);
    for (unsigned k = i; k < sizeof(g_c) / 16; k += stride) cc[k] = z;
}

// ---------------------------------------------------------------------------
// Weight preprocessing: bf16 hi/lo split, gate-interleaved cols, SW128-swizzled
// ---------------------------------------------------------------------------
__global__ void init_weights_kernel(const float* __restrict__ W0,
                                    const float* __restrict__ b0,
                                    const float* __restrict__ Wl,
                                    const float* __restrict__ bl) {
    unsigned i = blockIdx.x * blockDim.x + threadIdx.x;
    unsigned stride = gridDim.x * blockDim.x;
    // l(64) x kt(4) x nb(4) x k(32) x n(64) -- fill both planes together
    const unsigned NE = 64u * 4u * 4u * 32u * 64u;
    for (unsigned e = i; e < NE; e += stride) {
        unsigned n  = e & 63u;
        unsigned k  = (e >> 6) & 31u;
        unsigned nb = (e >> 11) & 3u;
        unsigned kt = (e >> 13) & 3u;
        unsigned l  = e >> 15;
        unsigned np = nb * 64u + n;          // n' = hc*4 + g
        unsigned hc = np >> 2, g = np & 3u;
        unsigned col = g * 64u + hc;
        unsigned krow = kt * 32u + k;        // 0..63 below-h, 64..127 own-h
        float w = 0.0f;
        if (l == 0) {
            if (krow >= 64u) w = W0[(1u + (krow - 64u)) * NG + col];
        } else {
            w = Wl[((size_t)(l - 1) * 128u + krow) * NG + col];
        }
        __nv_bfloat16 hi = __float2bfloat16(w);
        __nv_bfloat16 lo = __float2bfloat16(w - __bfloat162float(hi));
        unsigned off = swz(k * 128u + n * 2u) >> 1;
        g_Wimg[l][kt][0][nb][off] = hi;
        g_Wimg[l][kt][1][nb][off] = lo;
    }
    for (unsigned e = i; e < 64u * 256u; e += stride) {
        unsigned l = e >> 8, np = e & 255u;
        unsigned hc = np >> 2, g = np & 3u;
        g_bias[l][np] = (l == 0) ? b0[g * 64u + hc] : bl[(l - 1) * NG + g * 64u + hc];
    }
    for (unsigned np = i; np < 256u; np += stride) {
        unsigned hc = np >> 2, g = np & 3u;
        g_w0r0[np] = W0[g * 64u + hc];
    }
}

// ---------------------------------------------------------------------------
__device__ __forceinline__ void wave_barrier(unsigned val) {
    __syncthreads();
    if (threadIdx.x == 0) {
        asm volatile("st.release.gpu.global.u32 [%0], %1;"
                     :: "l"(&g_flags[blockIdx.x]), "r"(val) : "memory");
    }
    if (threadIdx.x < GRID) {
        unsigned v;
        do {
            asm volatile("ld.acquire.gpu.global.u32 %0, [%1];"
                         : "=r"(v) : "l"(&g_flags[threadIdx.x]) : "memory");
        } while (v < val);
    }
    __syncthreads();
}

// ---------------------------------------------------------------------------
// One unit: cell (l,t), rows [j*32, j*32+32), all 256 gate-columns, K=128.
// ---------------------------------------------------------------------------
__device__ void do_unit(int l, int t, int j, char* smc, const float* __restrict__ x) {
    const int tid = threadIdx.x;
    const int lane = tid & 31;
    const int wid = tid >> 5;
    const int mb = wid & 1;       // m-block (16 rows)
    const int nb = wid >> 1;      // n-block (64 gate-cols)
    const int m0 = j * 32;
    const int par = t & 1;
    const int s0 = (l == 0) ? 2 : 0;

    const unsigned sA = smem_u32(smc);
    const unsigned sW = sA + 16384u;

    // ---- prefetch first W tile (dep-free; overlaps flag wait) ----
    {
        const char* wsrc = reinterpret_cast<const char*>(&g_Wimg[l][s0][0][0][0]);
        unsigned dst = sW + (unsigned)(s0 & 1) * 32768u;
        for (int i = tid; i < 2048; i += NTHR)
            cp_async16(dst + (unsigned)i * 16u, wsrc + i * 16);
        cp_commit();
    }

    // ---- dataflow wait: (l-1,t), (l,t-1), anti (l+1,t-2), chunk j ----
    if (tid < 3) {
        const unsigned* f = nullptr;
        if (tid == 0)      { if (l > 0) f = &g_done[l - 1][t][j]; }
        else if (tid == 1) { if (t > 0) f = &g_done[l][t - 1][j]; }
        else               { if (l < TT - 1 && t >= 2) f = &g_done[l + 1][t - 2][j]; }
        if (f) {
            unsigned v;
            do {
                asm volatile("ld.acquire.gpu.global.u32 %0, [%1];"
                             : "=r"(v) : "l"(f) : "memory");
            } while (!v);
        }
    }
    __syncthreads();

    // ---- stage A: [p][kb][mb][16m][64k] swizzled subtiles of 2KB ----
    if (l > 0) {
        for (int e = tid; e < 1024; e += NTHR) {
            int p = e >> 9, kb = (e >> 8) & 1, mbb = (e >> 7) & 1;
            int m = (e >> 3) & 15, seg = e & 7;
            const __nv_bfloat16* src =
                &g_h[p][kb ? (par ^ 1) : par][kb ? l : (l - 1)][m0 + mbb * 16 + m][seg * 8];
            unsigned dst = sA + (unsigned)(((p * 2 + kb) * 2 + mbb) * 2048) +
                           swz((unsigned)(m * 128 + seg * 16));
            cp_async16(dst, src);
        }
    } else {
        for (int e = tid; e < 512; e += NTHR) {
            int p = e >> 8, mbb = (e >> 7) & 1;
            int m = (e >> 3) & 15, seg = e & 7;
            const __nv_bfloat16* src = &g_h[p][par ^ 1][0][m0 + mbb * 16 + m][seg * 8];
            unsigned dst = sA + (unsigned)(((p * 2 + 1) * 2 + mbb) * 2048) +
                           swz((unsigned)(m * 128 + seg * 16));
            cp_async16(dst, src);
        }
    }
    cp_commit();

    // ---- accumulators ----
    float acc[8][4];
#pragma unroll
    for (int q = 0; q < 8; ++q)
#pragma unroll
        for (int r = 0; r < 4; ++r) acc[q][r] = 0.0f;

    const int mat = lane >> 3, mr = lane & 7;

    // ---- k-tile loop (32-k tiles, W double-buffered) ----
    for (int s = s0; s < 4; ++s) {
        if (s > s0) __syncthreads();  // done reading buf[(s+1)&1] from tile s-1
        if (s < 3) {
            const char* wsrc = reinterpret_cast<const char*>(&g_Wimg[l][s + 1][0][0][0]);
            unsigned dst = sW + (unsigned)((s + 1) & 1) * 32768u;
            for (int i = tid; i < 2048; i += NTHR)
                cp_async16(dst + (unsigned)i * 16u, wsrc + i * 16);
            cp_commit();
            asm volatile("cp.async.wait_group 1;\n" ::: "memory");
        } else {
            asm volatile("cp.async.wait_group 0;\n" ::: "memory");
        }
        __syncthreads();

        const unsigned wb = sW + (unsigned)(s & 1) * 32768u;
        const int kb = s >> 1;
#pragma unroll
        for (int ks = 0; ks < 2; ++ks) {
            const unsigned kin = (unsigned)(((s & 1) * 2 + ks) * 16);
            // A fragments (hi, lo planes)
            unsigned abyte = (unsigned)(((mat & 1) * 8 + mr) * 128) +
                             (kin + (unsigned)((mat >> 1) * 8)) * 2u;
            unsigned ah[4], al[4];
            ldsm_x4(ah, sA + (unsigned)(((0 * 2 + kb) * 2 + mb) * 2048) + swz(abyte));
            ldsm_x4(al, sA + (unsigned)(((1 * 2 + kb) * 2 + mb) * 2048) + swz(abyte));
            // B fragments + MMAs per n16 pair
            unsigned brow = (unsigned)((ks * 16 + (mat & 1) * 8 + mr) * 128);
#pragma unroll
            for (int np = 0; np < 4; ++np) {
                unsigned noff = (unsigned)((np * 16 + (mat >> 1) * 8) * 2);
                unsigned bh[4], bl4[4];
                ldsm_x4_t(bh,  wb + (unsigned)((0 * 4 + nb) * 4096) + swz(brow + noff));
                ldsm_x4_t(bl4, wb + (unsigned)((1 * 4 + nb) * 4096) + swz(brow + noff));
                float* c0 = acc[np * 2 + 0];
                float* c1 = acc[np * 2 + 1];
                mma_bf16(c0, ah, bh[0], bh[1]);
                mma_bf16(c0, ah, bl4[0], bl4[1]);
                mma_bf16(c0, al, bh[0], bh[1]);
                mma_bf16(c1, ah, bh[2], bh[3]);
                mma_bf16(c1, ah, bl4[2], bl4[3]);
                mma_bf16(c1, al, bh[2], bh[3]);
            }
        }
    }

    // ---- Z buffer: accumulators -> smem (aliases A + W buf0; safe after sync) ----
    __syncthreads();
    float* Z = reinterpret_cast<float*>(smc);
    {
        const int cr = lane >> 2, cc = (lane & 3) * 2;
        const int row0 = mb * 16 + cr;
#pragma unroll
        for (int np = 0; np < 4; ++np) {
#pragma unroll
            for (int h8 = 0; h8 < 2; ++h8) {
                int npr = nb * 64 + np * 16 + h8 * 8 + cc;
                float* a4 = acc[np * 2 + h8];
                *reinterpret_cast<float2*>(&Z[row0 * ZSTRIDE + npr]) =
                    make_float2(a4[0], a4[1]);
                *reinterpret_cast<float2*>(&Z[(row0 + 8) * ZSTRIDE + npr]) =
                    make_float2(a4[2], a4[3]);
            }
        }
    }
    __syncthreads();

    // ---- gate epilogue: thread = (row = tid&31, hc block = (tid>>5)*8) ----
    {
        const int row = tid & 31;
        const int hcb = (tid >> 5) * 8;
        const int b = m0 + row;
        const float xv = (l == 0) ? x[(size_t)b * TT + t] : 0.0f;
        float4 c0 = __ldcg(reinterpret_cast<const float4*>(&g_c[l][b][hcb]));
        float4 c1 = __ldcg(reinterpret_cast<const float4*>(&g_c[l][b][hcb + 4]));
        float cold[8] = {c0.x, c0.y, c0.z, c0.w, c1.x, c1.y, c1.z, c1.w};
        float cnew[8], hnew[8];
#pragma unroll
        for (int q = 0; q < 8; ++q) {
            int np4 = (hcb + q) * 4;
            float2 zij = *reinterpret_cast<const float2*>(&Z[row * ZSTRIDE + np4]);
            float2 zfo = *reinterpret_cast<const float2*>(&Z[row * ZSTRIDE + np4 + 2]);
            float4 bv = *reinterpret_cast<const float4*>(&g_bias[l][np4]);
            float zi = zij.x + bv.x, zj = zij.y + bv.y;
            float zf = zfo.x + bv.z, zo = zfo.y + bv.w;
            if (l == 0) {
                float4 wv = *reinterpret_cast<const float4*>(&g_w0r0[np4]);
                zi += xv * wv.x; zj += xv * wv.y; zf += xv * wv.z; zo += xv * wv.w;
            }
            float cn = cold[q] * sigf(zf) + sigf(zi) * tanh_(zj);
            cnew[q] = cn;
            hnew[q] = tanh_(cn) * sigf(zo);
        }
        *reinterpret_cast<float4*>(&g_c[l][b][hcb]) =
            make_float4(cnew[0], cnew[1], cnew[2], cnew[3]);
        *reinterpret_cast<float4*>(&g_c[l][b][hcb + 4]) =
            make_float4(cnew[4], cnew[5], cnew[6], cnew[7]);
        unsigned hi_u[4], lo_u[4];
#pragma unroll
        for (int q2 = 0; q2 < 4; ++q2) {
            __nv_bfloat16 h0 = __float2bfloat16(hnew[2 * q2]);
            __nv_bfloat16 h1 = __float2bfloat16(hnew[2 * q2 + 1]);
            __nv_bfloat16 l0 = __float2bfloat16(hnew[2 * q2] - __bfloat162float(h0));
            __nv_bfloat16 l1 = __float2bfloat16(hnew[2 * q2 + 1] - __bfloat162float(h1));
            __nv_bfloat162 ph(h0, h1), pl(l0, l1);
            hi_u[q2] = *reinterpret_cast<unsigned*>(&ph);
            lo_u[q2] = *reinterpret_cast<unsigned*>(&pl);
        }
        *reinterpret_cast<uint4*>(&g_h[0][par][l][b][hcb]) =
            make_uint4(hi_u[0], hi_u[1], hi_u[2], hi_u[3]);
        *reinterpret_cast<uint4*>(&g_h[1][par][l][b][hcb]) =
            make_uint4(lo_u[0], lo_u[1], lo_u[2], lo_u[3]);
        if (l == TT - 1) {
            *reinterpret_cast<float4*>(&g_outs[b][t][hcb]) =
                make_float4(hnew[0], hnew[1], hnew[2], hnew[3]);
            *reinterpret_cast<float4*>(&g_outs[b][t][hcb + 4]) =
                make_float4(hnew[4], hnew[5], hnew[6], hnew[7]);
        }
    }

    __syncthreads();
    if (tid == 0) {
        asm volatile("st.release.gpu.global.u32 [%0], %1;"
                     :: "l"(&g_done[l][t][j]), "r"(1u) : "memory");
    }
}

// ---------------------------------------------------------------------------
__global__ __launch_bounds__(NTHR, 2)
void lstm_mma_kernel(const float* __restrict__ x,
                     const float* __restrict__ labels,
                     const float* __restrict__ Wd,
                     const float* __restrict__ bd,
                     float* __restrict__ out, int out_size) {
    extern __shared__ __align__(1024) char smc[];
    const int tid = threadIdx.x;
    const int bid = blockIdx.x;

    unsigned off = 0;
    for (int w = 0; w < 2 * TT - 1; ++w) {
        const int lo = (w > TT - 1) ? (w - (TT - 1)) : 0;
        const int hi = (w < TT - 1) ? w : (TT - 1);
        const int width = hi - lo + 1;
        const int units = 4 * width;
        int u = (int)((unsigned)(bid - off) & (GRID - 1));
        if (u < units) {
            const int l = lo + (u >> 2);
            const int t = w - l;
            do_unit(l, t, u & 3, smc, x);
        }
        off += (unsigned)units;
    }

    wave_barrier(1u);

    for (int idx = bid * NTHR + tid; idx < BB * TT; idx += GRID * NTHR) {
        int b = idx >> 6, t = idx & 63;
        const float* o = &g_outs[b][t][0];
        const float* wv = Wd + (size_t)t * HH;
        float s = bd[t];
#pragma unroll
        for (int h = 0; h < HH; ++h) s += __ldcg(o + h) * wv[h];
        out[idx] = fmaxf(s, 0.0f);
    }
    wave_barrier(2u);

    if (bid == 0) {
        float* red = reinterpret_cast<float*>(smc);
        float s = 0.0f;
        for (int i = tid; i < BB * TT; i += NTHR) {
            float d = labels[i] - __ldcg(out + i);
            s += d * d;
        }
        red[tid] = s;
        __syncthreads();
        for (int o2 = NTHR / 2; o2 > 0; o2 >>= 1) {
            if (tid < o2) red[tid] += red[tid + o2];
            __syncthreads();
        }
        if (tid == 0 && out_size > BB * TT)
            out[BB * TT] = red[0] / (float)(BB * TT);
    }
}

// ---------------------------------------------------------------------------
extern "C" void kernel_launch(void* const* d_in, const int* in_sizes, int n_in,
                              void* d_out, int out_size) {
    const float* x      = (const float*)d_in[0];
    const float* labels = (const float*)d_in[1];
    const float* W0     = (const float*)d_in[2];
    const float* b0     = (const float*)d_in[3];
    const float* Wl     = (const float*)d_in[4];
    const float* bl     = (const float*)d_in[5];
    const float* Wd     = (const float*)d_in[6];
    const float* bd     = (const float*)d_in[7];
    float* out = (float*)d_out;

    static bool attr_set = false;
    if (!attr_set) {
        cudaFuncSetAttribute(lstm_mma_kernel,
                             cudaFuncAttributeMaxDynamicSharedMemorySize, SMEM_BYTES);
        attr_set = true;
    }

    init_state_kernel<<<1024, 256>>>();
    init_weights_kernel<<<512, 256>>>(W0, b0, Wl, bl);
    lstm_mma_kernel<<<GRID, NTHR, SMEM_BYTES>>>(x, labels, Wd, bd, out, out_size);
}